// round 2
// baseline (speedup 1.0000x reference)
#include <cuda_runtime.h>

#define NN 50000      // nodes
#define NE 800000     // edges
#define NP 50048      // nodes padded to multiple of 128
#define ED 64         // edge feature dim
#define HID 152
#define NA_LD 152     // row stride of neighbor-agg buffer

// ---------------- scratch (device globals; no allocation allowed) ----------
__device__ float g_deg[NP];
__device__ float g_eagg[(size_t)NP * ED];
__device__ float g_na[(size_t)NP * NA_LD];
__device__ float g_h1[(size_t)NP * HID];
__device__ float g_h2[(size_t)NP * HID];
__device__ float g_xc[(size_t)NP * 384];
__device__ float g_wc1[192 * 208];
__device__ float g_wc2[192 * 384];
__device__ float g_wc3[64 * 384];

// ---------------- utility ---------------------------------------------------
__global__ void k_zero(float* __restrict__ p, int n) {
    int t = blockIdx.x * blockDim.x + threadIdx.x;
    if (t < n) p[t] = 0.f;
}

// ---------------- edge-feature aggregation + degree (once per launch) -------
__global__ void k_edge_agg(const float* __restrict__ ef, const int* __restrict__ dst) {
    int t = blockIdx.x * blockDim.x + threadIdx.x;
    if (t >= NE * 16) return;
    int e = t >> 4, c = t & 15;
    int d = dst[e];
    float4 v = *(const float4*)(ef + (size_t)e * ED + c * 4);
    float* o = g_eagg + (size_t)d * ED + c * 4;
    atomicAdd(o + 0, v.x); atomicAdd(o + 1, v.y);
    atomicAdd(o + 2, v.z); atomicAdd(o + 3, v.w);
    if (c == 0) atomicAdd(&g_deg[d], 1.f);
}

// ---------------- scatter-add of node features over edges -------------------
template <int NC>   // NC = Fin/4 chunks of float4 per edge
__global__ void k_scatter(const float* __restrict__ X, int ldx,
                          const int* __restrict__ src, const int* __restrict__ dst) {
    int t = blockIdx.x * blockDim.x + threadIdx.x;
    if (t >= NE * NC) return;
    int e = t / NC;
    int c = t - e * NC;
    int s = src[e], d = dst[e];
    float4 v = *(const float4*)(X + (size_t)s * ldx + c * 4);
    float* o = g_na + (size_t)d * NA_LD + c * 4;
    atomicAdd(o + 0, v.x); atomicAdd(o + 1, v.y);
    atomicAdd(o + 2, v.z); atomicAdd(o + 3, v.w);
}

// ---------------- build fused input  Xc = [x | inv*na | inv*eagg | ind | 0pad]
template <int FIN, int KP>
__global__ void k_xc(const float* __restrict__ X, int ldx) {
    int t = blockIdx.x * blockDim.x + threadIdx.x;
    if (t >= NP * KP) return;
    int v = t / KP;
    int col = t - v * KP;
    float out = 0.f;
    if (v < NN) {
        float dg = g_deg[v];
        if (col < FIN) {
            out = X[(size_t)v * ldx + col];
        } else {
            float inv = 1.f / fmaxf(dg, 1.f);
            if (col < 2 * FIN)            out = inv * g_na[(size_t)v * NA_LD + (col - FIN)];
            else if (col < 2 * FIN + ED)  out = inv * g_eagg[(size_t)v * ED + (col - 2 * FIN)];
            else if (col == 2 * FIN + ED) out = (dg > 0.f) ? 1.f : 0.f;
        }
    }
    g_xc[(size_t)v * KP + col] = out;
}

// ---------------- build fused weight Wc = [Wa_self | Wa_h@Wm_n | Wa_h@Wm_e | Wa_h@bm]
__global__ void k_wc(const float* __restrict__ Wm, const float* __restrict__ bm,
                     const float* __restrict__ Wa, float* __restrict__ Wc,
                     int Fin, int Fm, int Fout, int Kp) {
    int col = blockIdx.x * blockDim.x + threadIdx.x;
    int j = blockIdx.y;
    int K1 = 2 * Fin + ED + 1;
    if (col >= K1 || j >= Fout) return;
    int WmK = Fin + ED;
    int WaK = Fin + Fm;
    const float* wah = Wa + (size_t)j * WaK + Fin;
    float val;
    if (col < Fin) {
        val = Wa[(size_t)j * WaK + col];
    } else if (col < 2 * Fin) {
        int i = col - Fin;
        float s = 0.f;
        for (int t = 0; t < Fm; t++) s += wah[t] * Wm[(size_t)t * WmK + i];
        val = s;
    } else if (col < 2 * Fin + ED) {
        int i = col - 2 * Fin;
        float s = 0.f;
        for (int t = 0; t < Fm; t++) s += wah[t] * Wm[(size_t)t * WmK + Fin + i];
        val = s;
    } else {
        float s = 0.f;
        for (int t = 0; t < Fm; t++) s += wah[t] * bm[t];
        val = s;
    }
    Wc[(size_t)j * Kp + col] = val;
}

// ---------------- tiled fp32 GEMM: C = relu(Xc @ Wc^T + bias) ---------------
// BM=128, BN=64, BK=16, 256 threads, 8x4 microtile
__global__ __launch_bounds__(256) void k_gemm(
    const float* __restrict__ A, const float* __restrict__ B,
    const float* __restrict__ bias, float* __restrict__ C,
    int M, int Nout, int Kp, int ldc) {
    __shared__ float As[16][132];
    __shared__ float Bs[16][68];
    const int m0 = blockIdx.x * 128;
    const int n0 = blockIdx.y * 64;
    const int tid = threadIdx.x;
    const int tx = tid & 15;   // 4 n-cols
    const int ty = tid >> 4;   // 8 m-rows
    float acc[8][4];
#pragma unroll
    for (int i = 0; i < 8; i++)
#pragma unroll
        for (int j = 0; j < 4; j++) acc[i][j] = 0.f;

    for (int k0 = 0; k0 < Kp; k0 += 16) {
#pragma unroll
        for (int i = 0; i < 2; i++) {
            int idx = tid + i * 256;
            int r = idx >> 2, kq = (idx & 3) << 2;
            float4 v = *(const float4*)(A + (size_t)(m0 + r) * Kp + (k0 + kq));
            As[kq + 0][r] = v.x; As[kq + 1][r] = v.y;
            As[kq + 2][r] = v.z; As[kq + 3][r] = v.w;
        }
        {
            int r = tid >> 2, kq = (tid & 3) << 2;
            float4 v = *(const float4*)(B + (size_t)(n0 + r) * Kp + (k0 + kq));
            Bs[kq + 0][r] = v.x; Bs[kq + 1][r] = v.y;
            Bs[kq + 2][r] = v.z; Bs[kq + 3][r] = v.w;
        }
        __syncthreads();
#pragma unroll
        for (int k = 0; k < 16; k++) {
            float4 a0 = *(const float4*)&As[k][ty * 8];
            float4 a1 = *(const float4*)&As[k][ty * 8 + 4];
            float4 b  = *(const float4*)&Bs[k][tx * 4];
            float av[8] = {a0.x, a0.y, a0.z, a0.w, a1.x, a1.y, a1.z, a1.w};
            float bv[4] = {b.x, b.y, b.z, b.w};
#pragma unroll
            for (int i = 0; i < 8; i++)
#pragma unroll
                for (int j = 0; j < 4; j++) acc[i][j] += av[i] * bv[j];
        }
        __syncthreads();
    }
#pragma unroll
    for (int j = 0; j < 4; j++) {
        int n = n0 + tx * 4 + j;
        if (n >= Nout) continue;
        float bb = bias[n];
#pragma unroll
        for (int i = 0; i < 8; i++) {
            int m = m0 + ty * 8 + i;
            if (m < M) C[(size_t)m * ldc + n] = fmaxf(acc[i][j] + bb, 0.f);
        }
    }
}

// ---------------- driver ----------------------------------------------------
static inline void Z(float* p, size_t n) {
    k_zero<<<(int)((n + 255) / 256), 256>>>(p, (int)n);
}

extern "C" void kernel_launch(void* const* d_in, const int* in_sizes, int n_in,
                              void* d_out, int out_size) {
    const float* nf  = (const float*)d_in[0];
    const float* ef  = (const float*)d_in[1];
    const float* Wm1 = (const float*)d_in[2];  const float* bm1 = (const float*)d_in[3];
    const float* Wa1 = (const float*)d_in[4];  const float* ba1 = (const float*)d_in[5];
    const float* Wm2 = (const float*)d_in[6];  const float* bm2 = (const float*)d_in[7];
    const float* Wa2 = (const float*)d_in[8];  const float* ba2 = (const float*)d_in[9];
    const float* Wm3 = (const float*)d_in[10]; const float* bm3 = (const float*)d_in[11];
    const float* Wa3 = (const float*)d_in[12]; const float* ba3 = (const float*)d_in[13];
    const int* src = (const int*)d_in[14];
    const int* dst = (const int*)d_in[15];
    float* out = (float*)d_out;

    float *p_deg, *p_eagg, *p_na, *p_h1, *p_h2, *p_xc, *p_wc1, *p_wc2, *p_wc3;
    cudaGetSymbolAddress((void**)&p_deg,  g_deg);
    cudaGetSymbolAddress((void**)&p_eagg, g_eagg);
    cudaGetSymbolAddress((void**)&p_na,   g_na);
    cudaGetSymbolAddress((void**)&p_h1,   g_h1);
    cudaGetSymbolAddress((void**)&p_h2,   g_h2);
    cudaGetSymbolAddress((void**)&p_xc,   g_xc);
    cudaGetSymbolAddress((void**)&p_wc1,  g_wc1);
    cudaGetSymbolAddress((void**)&p_wc2,  g_wc2);
    cudaGetSymbolAddress((void**)&p_wc3,  g_wc3);

    // graph-constant precomputes
    Z(p_deg, NP);
    Z(p_eagg, (size_t)NP * ED);
    Z(p_wc1, 192 * 208);
    Z(p_wc2, 192 * 384);
    Z(p_wc3, 64 * 384);
    k_edge_agg<<<(NE * 16 + 255) / 256, 256>>>(ef, dst);
    k_wc<<<dim3((193 + 127) / 128, 152), 128>>>(Wm1, bm1, Wa1, p_wc1, 64, 152, 152, 208);
    k_wc<<<dim3((369 + 127) / 128, 152), 128>>>(Wm2, bm2, Wa2, p_wc2, 152, 152, 152, 384);
    k_wc<<<dim3((369 + 127) / 128, 64), 128>>>(Wm3, bm3, Wa3, p_wc3, 152, 64, 64, 384);

    // ---- layer 1 (Fin=64 -> 152) ----
    Z(p_na, (size_t)NP * NA_LD);
    k_scatter<16><<<(NE * 16 + 255) / 256, 256>>>(nf, 64, src, dst);
    k_xc<64, 208><<<(NP * 208 + 255) / 256, 256>>>(nf, 64);
    k_gemm<<<dim3(NP / 128, 3), 256>>>(p_xc, p_wc1, ba1, p_h1, NN, 152, 208, HID);

    // ---- layer 2 (152 -> 152) ----
    Z(p_na, (size_t)NP * NA_LD);
    k_scatter<38><<<(NE * 38 + 255) / 256, 256>>>(p_h1, HID, src, dst);
    k_xc<152, 384><<<(NP * 384 + 255) / 256, 256>>>(p_h1, HID);
    k_gemm<<<dim3(NP / 128, 3), 256>>>(p_xc, p_wc2, ba2, p_h2, NN, 152, 384, HID);

    // ---- layer 3 (152 -> 64) ----
    Z(p_na, (size_t)NP * NA_LD);
    k_scatter<38><<<(NE * 38 + 255) / 256, 256>>>(p_h2, HID, src, dst);
    k_xc<152, 384><<<(NP * 384 + 255) / 256, 256>>>(p_h2, HID);
    k_gemm<<<dim3(NP / 128, 1), 256>>>(p_xc, p_wc3, ba3, out, NN, 64, 384, 64);
}

// round 5
// speedup vs baseline: 2.9078x; 2.9078x over previous
#include <cuda_runtime.h>

#define NN 50000      // nodes
#define NE 800000     // edges
#define NP 50048      // nodes padded to multiple of 128
#define NB 98         // scan blocks: ceil(NP/512)
#define ED 64         // edge feature dim
#define HID 152

// ---------------- scratch (device globals; no allocation allowed) ----------
__device__ int   g_cnt[NP];
__device__ int   g_fill[NP];
__device__ int   g_base[NP + 1];
__device__ int   g_bsum[128];
__device__ int   g_src[NE];      // src node per edge, CSR-ordered by dst
__device__ int   g_eid[NE];      // original edge id, CSR-ordered by dst
__device__ float g_eagg[(size_t)NP * ED];
__device__ float g_h1[(size_t)NP * HID];
__device__ float g_h2[(size_t)NP * HID];
__device__ float g_xc1[(size_t)NP * 208];
__device__ float g_xc2[(size_t)NP * 384];
__device__ float g_wc1[192 * 208];
__device__ float g_wc2[192 * 384];
__device__ float g_wc3[64 * 384];

// ---------------- utility ---------------------------------------------------
__global__ void k_zero_f(float* __restrict__ p, int n) {
    int t = blockIdx.x * blockDim.x + threadIdx.x;
    if (t < n) p[t] = 0.f;
}
__global__ void k_zero_i(int* __restrict__ p, int n) {
    int t = blockIdx.x * blockDim.x + threadIdx.x;
    if (t < n) p[t] = 0;
}

// ---------------- CSR build -------------------------------------------------
__global__ void k_count(const int* __restrict__ dst) {
    int t = blockIdx.x * blockDim.x + threadIdx.x;
    if (t < NE) atomicAdd(&g_cnt[dst[t]], 1);
}

__global__ void k_scan1() {
    __shared__ int sh[512];
    int b = blockIdx.x, t = threadIdx.x, i = b * 512 + t;
    int v = (i < NP) ? g_cnt[i] : 0;
    sh[t] = v;
    __syncthreads();
#pragma unroll
    for (int o = 1; o < 512; o <<= 1) {
        int x = (t >= o) ? sh[t - o] : 0;
        __syncthreads();
        sh[t] += x;
        __syncthreads();
    }
    if (i < NP) g_base[i + 1] = sh[t];
    if (t == 511) g_bsum[b] = sh[511];
}

__global__ void k_scan2() {
    if (threadIdx.x == 0) {
        int s = 0;
        for (int b = 0; b < NB; b++) { int c = g_bsum[b]; g_bsum[b] = s; s += c; }
    }
}

__global__ void k_scan3() {
    int i = blockIdx.x * blockDim.x + threadIdx.x;
    if (i < NP) g_base[i + 1] += g_bsum[i >> 9];
    if (i == 0) g_base[0] = 0;
}

__global__ void k_fill(const int* __restrict__ src, const int* __restrict__ dst) {
    int t = blockIdx.x * blockDim.x + threadIdx.x;
    if (t >= NE) return;
    int d = dst[t];
    int p = g_base[d] + atomicAdd(&g_fill[d], 1);
    g_src[p] = src[t];
    g_eid[p] = t;
}

// ---------------- edge-feature gather-sum per dst node ----------------------
__global__ void k_gather_e(const float* __restrict__ ef) {
    int w = (blockIdx.x * blockDim.x + threadIdx.x) >> 5;
    int lane = threadIdx.x & 31;
    if (w >= NN || lane >= 16) return;
    int e0 = g_base[w], e1 = g_base[w + 1];
    float4 a = {0.f, 0.f, 0.f, 0.f};
    for (int e = e0; e < e1; e++) {
        int id = g_eid[e];
        float4 v = *(const float4*)(ef + (size_t)id * ED + lane * 4);
        a.x += v.x; a.y += v.y; a.z += v.z; a.w += v.w;
    }
    *(float4*)(g_eagg + (size_t)w * ED + lane * 4) = a;
}

// ---------------- static columns of fused GEMM input (once per launch) ------
// layout per row v: [0,FIN)=x  [FIN,2FIN)=inv*na  [2FIN,2FIN+64)=inv*eagg
//                   [2FIN+64]=indicator  rest=0 ; pad rows fully 0
template <int KP, int FIN>
__global__ void k_static(float* __restrict__ XC) {
    int t = blockIdx.x * blockDim.x + threadIdx.x;
    if (t >= NP * KP) return;
    int v = t / KP, col = t - v * KP;
    float* p = XC + (size_t)v * KP + col;
    if (v >= NN) { *p = 0.f; return; }
    if (col < 2 * FIN) return;                 // dynamic: written by gather each layer
    int dg = g_cnt[v];
    float val = 0.f;
    if (col < 2 * FIN + 64) {
        float inv = 1.f / (float)max(dg, 1);
        val = inv * g_eagg[(size_t)v * ED + (col - 2 * FIN)];
    } else if (col == 2 * FIN + 64) {
        val = (dg > 0) ? 1.f : 0.f;
    }
    *p = val;
}

// ---------------- per-layer: copy x + gather mean of src rows into XC -------
template <int NC4, int FIN, int KP>
__global__ void k_gather(const float* __restrict__ X, int ldx, float* __restrict__ XC) {
    int w = (blockIdx.x * blockDim.x + threadIdx.x) >> 5;
    int lane = threadIdx.x & 31;
    if (w >= NN) return;
    int e0 = g_base[w], e1 = g_base[w + 1];
    int c0 = lane, c1 = lane + 32;
    float4 a0 = {0.f, 0.f, 0.f, 0.f};
    float4 a1 = {0.f, 0.f, 0.f, 0.f};
    for (int e = e0; e < e1; e++) {
        int s = g_src[e];
        const float4* row = (const float4*)(X + (size_t)s * ldx);
        if (c0 < NC4) {
            float4 v = row[c0];
            a0.x += v.x; a0.y += v.y; a0.z += v.z; a0.w += v.w;
        }
        if (NC4 > 32 && c1 < NC4) {
            float4 v = row[c1];
            a1.x += v.x; a1.y += v.y; a1.z += v.z; a1.w += v.w;
        }
    }
    float inv = 1.f / fmaxf((float)(e1 - e0), 1.f);
    float4* out = (float4*)(XC + (size_t)w * KP);
    const float4* xrow = (const float4*)(X + (size_t)w * ldx);
    if (c0 < NC4) {
        out[c0] = xrow[c0];
        float4 r; r.x = a0.x * inv; r.y = a0.y * inv; r.z = a0.z * inv; r.w = a0.w * inv;
        out[FIN / 4 + c0] = r;
    }
    if (NC4 > 32 && c1 < NC4) {
        out[c1] = xrow[c1];
        float4 r; r.x = a1.x * inv; r.y = a1.y * inv; r.z = a1.z * inv; r.w = a1.w * inv;
        out[FIN / 4 + c1] = r;
    }
}

// ---------------- build fused weight Wc = [Wa_self | Wa_h@Wm_n | Wa_h@Wm_e | Wa_h@bm]
__global__ void k_wc(const float* __restrict__ Wm, const float* __restrict__ bm,
                     const float* __restrict__ Wa, float* __restrict__ Wc,
                     int Fin, int Fm, int Fout, int Kp) {
    int col = blockIdx.x * blockDim.x + threadIdx.x;
    int j = blockIdx.y;
    int K1 = 2 * Fin + ED + 1;
    if (col >= K1 || j >= Fout) return;
    int WmK = Fin + ED;
    int WaK = Fin + Fm;
    const float* wah = Wa + (size_t)j * WaK + Fin;
    float val;
    if (col < Fin) {
        val = Wa[(size_t)j * WaK + col];
    } else if (col < 2 * Fin) {
        int i = col - Fin;
        float s = 0.f;
        for (int t = 0; t < Fm; t++) s += wah[t] * Wm[(size_t)t * WmK + i];
        val = s;
    } else if (col < 2 * Fin + ED) {
        int i = col - 2 * Fin;
        float s = 0.f;
        for (int t = 0; t < Fm; t++) s += wah[t] * Wm[(size_t)t * WmK + Fin + i];
        val = s;
    } else {
        float s = 0.f;
        for (int t = 0; t < Fm; t++) s += wah[t] * bm[t];
        val = s;
    }
    Wc[(size_t)j * Kp + col] = val;
}

// ---------------- tiled fp32 GEMM: C = relu(Xc @ Wc^T + bias) ---------------
// BM=128, BN=64, BK=16, 128 threads, 8x8 microtile
__global__ __launch_bounds__(128) void k_gemm(
    const float* __restrict__ A, const float* __restrict__ B,
    const float* __restrict__ bias, float* __restrict__ C,
    int M, int Nout, int Kp, int ldc) {
    __shared__ float As[16][132];
    __shared__ float Bs[16][68];
    const int m0 = blockIdx.x * 128;
    const int n0 = blockIdx.y * 64;
    const int tid = threadIdx.x;
    const int tx = tid & 7;    // 8 n-groups of 8
    const int ty = tid >> 3;   // 16 m-groups of 8
    float acc[8][8];
#pragma unroll
    for (int i = 0; i < 8; i++)
#pragma unroll
        for (int j = 0; j < 8; j++) acc[i][j] = 0.f;

    for (int k0 = 0; k0 < Kp; k0 += 16) {
#pragma unroll
        for (int i = 0; i < 4; i++) {
            int idx = tid + i * 128;
            int r = idx >> 2, kq = (idx & 3) << 2;
            float4 v = *(const float4*)(A + (size_t)(m0 + r) * Kp + (k0 + kq));
            As[kq + 0][r] = v.x; As[kq + 1][r] = v.y;
            As[kq + 2][r] = v.z; As[kq + 3][r] = v.w;
        }
#pragma unroll
        for (int i = 0; i < 2; i++) {
            int idx = tid + i * 128;
            int r = idx >> 2, kq = (idx & 3) << 2;
            float4 v = *(const float4*)(B + (size_t)(n0 + r) * Kp + (k0 + kq));
            Bs[kq + 0][r] = v.x; Bs[kq + 1][r] = v.y;
            Bs[kq + 2][r] = v.z; Bs[kq + 3][r] = v.w;
        }
        __syncthreads();
#pragma unroll
        for (int k = 0; k < 16; k++) {
            float4 a0 = *(const float4*)&As[k][ty * 8];
            float4 a1 = *(const float4*)&As[k][ty * 8 + 4];
            float4 b0 = *(const float4*)&Bs[k][tx * 8];
            float4 b1 = *(const float4*)&Bs[k][tx * 8 + 4];
            float av[8] = {a0.x, a0.y, a0.z, a0.w, a1.x, a1.y, a1.z, a1.w};
            float bv[8] = {b0.x, b0.y, b0.z, b0.w, b1.x, b1.y, b1.z, b1.w};
#pragma unroll
            for (int i = 0; i < 8; i++)
#pragma unroll
                for (int j = 0; j < 8; j++) acc[i][j] += av[i] * bv[j];
        }
        __syncthreads();
    }
#pragma unroll
    for (int j = 0; j < 8; j++) {
        int n = n0 + tx * 8 + j;
        if (n >= Nout) continue;
        float bb = bias[n];
#pragma unroll
        for (int i = 0; i < 8; i++) {
            int m = m0 + ty * 8 + i;
            if (m < M) C[(size_t)m * ldc + n] = fmaxf(acc[i][j] + bb, 0.f);
        }
    }
}

// ---------------- driver ----------------------------------------------------
extern "C" void kernel_launch(void* const* d_in, const int* in_sizes, int n_in,
                              void* d_out, int out_size) {
    const float* nf  = (const float*)d_in[0];
    const float* ef  = (const float*)d_in[1];
    const float* Wm1 = (const float*)d_in[2];  const float* bm1 = (const float*)d_in[3];
    const float* Wa1 = (const float*)d_in[4];  const float* ba1 = (const float*)d_in[5];
    const float* Wm2 = (const float*)d_in[6];  const float* bm2 = (const float*)d_in[7];
    const float* Wa2 = (const float*)d_in[8];  const float* ba2 = (const float*)d_in[9];
    const float* Wm3 = (const float*)d_in[10]; const float* bm3 = (const float*)d_in[11];
    const float* Wa3 = (const float*)d_in[12]; const float* ba3 = (const float*)d_in[13];
    const int* src = (const int*)d_in[14];
    const int* dst = (const int*)d_in[15];
    float* out = (float*)d_out;

    float *p_h1, *p_h2, *p_xc1, *p_xc2, *p_wc1, *p_wc2, *p_wc3;
    int *p_cnt, *p_fill;
    cudaGetSymbolAddress((void**)&p_cnt,  g_cnt);
    cudaGetSymbolAddress((void**)&p_fill, g_fill);
    cudaGetSymbolAddress((void**)&p_h1,   g_h1);
    cudaGetSymbolAddress((void**)&p_h2,   g_h2);
    cudaGetSymbolAddress((void**)&p_xc1,  g_xc1);
    cudaGetSymbolAddress((void**)&p_xc2,  g_xc2);
    cudaGetSymbolAddress((void**)&p_wc1,  g_wc1);
    cudaGetSymbolAddress((void**)&p_wc2,  g_wc2);
    cudaGetSymbolAddress((void**)&p_wc3,  g_wc3);

    const int GW = (NN * 32 + 255) / 256;   // warp-per-node grids

    // ---- CSR build (int atomics only; ~2.4M ops) ----
    k_zero_i<<<(NP + 255) / 256, 256>>>(p_cnt, NP);
    k_zero_i<<<(NP + 255) / 256, 256>>>(p_fill, NP);
    k_count<<<(NE + 255) / 256, 256>>>(dst);
    k_scan1<<<NB, 512>>>();
    k_scan2<<<1, 32>>>();
    k_scan3<<<(NP + 255) / 256, 256>>>();
    k_fill<<<(NE + 255) / 256, 256>>>(src, dst);

    // ---- graph-constant: edge-feature aggregation + static Xc columns ----
    k_gather_e<<<GW, 256>>>(ef);
    k_static<208,  64><<<(NP * 208 + 255) / 256, 256>>>(p_xc1);
    k_static<384, 152><<<(NP * 384 + 255) / 256, 256>>>(p_xc2);

    // ---- fused weights ----
    k_zero_f<<<(192 * 208 + 255) / 256, 256>>>(p_wc1, 192 * 208);
    k_zero_f<<<(192 * 384 + 255) / 256, 256>>>(p_wc2, 192 * 384);
    k_zero_f<<<(64 * 384 + 255) / 256, 256>>>(p_wc3, 64 * 384);
    k_wc<<<dim3(2, 152), 128>>>(Wm1, bm1, Wa1, p_wc1, 64, 152, 152, 208);
    k_wc<<<dim3(3, 152), 128>>>(Wm2, bm2, Wa2, p_wc2, 152, 152, 152, 384);
    k_wc<<<dim3(3, 64), 128>>>(Wm3, bm3, Wa3, p_wc3, 152, 64, 64, 384);

    // ---- layer 1 (64 -> 152) ----
    k_gather<16, 64, 208><<<GW, 256>>>(nf, 64, p_xc1);
    k_gemm<<<dim3(NP / 128, 3), 128>>>(p_xc1, p_wc1, ba1, p_h1, NN, 152, 208, HID);

    // ---- layer 2 (152 -> 152) ----
    k_gather<38, 152, 384><<<GW, 256>>>(p_h1, HID, p_xc2);
    k_gemm<<<dim3(NP / 128, 3), 128>>>(p_xc2, p_wc2, ba2, p_h2, NN, 152, 384, HID);

    // ---- layer 3 (152 -> 64) ----
    k_gather<38, 152, 384><<<GW, 256>>>(p_h2, HID, p_xc2);
    k_gemm<<<dim3(NP / 128, 1), 128>>>(p_xc2, p_wc3, ba3, out, NN, 64, 384, 64);
}

// round 8
// speedup vs baseline: 3.4354x; 1.1814x over previous
#include <cuda_runtime.h>
#include <cstdint>

#define NN 50000      // nodes
#define NE 800000     // edges
#define NP 50048      // nodes padded to multiple of 128
#define NB 98         // scan blocks: ceil(NP/512)
#define ED 64         // edge feature dim
#define HID 152

// ---------------- scratch (device globals; no allocation allowed) ----------
__device__ int   g_cnt[NP];
__device__ int   g_fill[NP];
__device__ int   g_base[NP + 1];
__device__ int   g_bsum[128];
__device__ int   g_src[NE];      // src node per edge, CSR-ordered by dst
__device__ int   g_eid[NE];      // original edge id, CSR-ordered by dst
__device__ float g_eagg[(size_t)NP * ED];
__device__ float g_h1[(size_t)NP * HID];
__device__ float g_h2[(size_t)NP * HID];
__device__ float g_xc1[(size_t)NP * 208];
__device__ float g_xc2[(size_t)NP * 384];
__device__ float g_wc1[192 * 208];
__device__ float g_wc2[192 * 384];
__device__ float g_wc3[64 * 384];

// ---------------- utility ---------------------------------------------------
__global__ void k_zero_f(float* __restrict__ p, int n) {
    int t = blockIdx.x * blockDim.x + threadIdx.x;
    if (t < n) p[t] = 0.f;
}
__global__ void k_zero_i(int* __restrict__ p, int n) {
    int t = blockIdx.x * blockDim.x + threadIdx.x;
    if (t < n) p[t] = 0;
}

// ---------------- CSR build -------------------------------------------------
__global__ void k_count(const int* __restrict__ dst) {
    int t = blockIdx.x * blockDim.x + threadIdx.x;
    if (t < NE) atomicAdd(&g_cnt[dst[t]], 1);
}

__global__ void k_scan1() {
    __shared__ int sh[512];
    int b = blockIdx.x, t = threadIdx.x, i = b * 512 + t;
    int v = (i < NP) ? g_cnt[i] : 0;
    sh[t] = v;
    __syncthreads();
#pragma unroll
    for (int o = 1; o < 512; o <<= 1) {
        int x = (t >= o) ? sh[t - o] : 0;
        __syncthreads();
        sh[t] += x;
        __syncthreads();
    }
    if (i < NP) g_base[i + 1] = sh[t];
    if (t == 511) g_bsum[b] = sh[511];
}

__global__ void k_scan2() {
    if (threadIdx.x == 0) {
        int s = 0;
        for (int b = 0; b < NB; b++) { int c = g_bsum[b]; g_bsum[b] = s; s += c; }
    }
}

__global__ void k_scan3() {
    int i = blockIdx.x * blockDim.x + threadIdx.x;
    if (i < NP) g_base[i + 1] += g_bsum[i >> 9];
    if (i == 0) g_base[0] = 0;
}

__global__ void k_fill(const int* __restrict__ src, const int* __restrict__ dst) {
    int t = blockIdx.x * blockDim.x + threadIdx.x;
    if (t >= NE) return;
    int d = dst[t];
    int p = g_base[d] + atomicAdd(&g_fill[d], 1);
    g_src[p] = src[t];
    g_eid[p] = t;
}

// ---------------- edge-feature gather-sum per dst node ----------------------
__global__ void k_gather_e(const float* __restrict__ ef) {
    int w = (blockIdx.x * blockDim.x + threadIdx.x) >> 5;
    int lane = threadIdx.x & 31;
    if (w >= NN || lane >= 16) return;
    int e0 = g_base[w], e1 = g_base[w + 1];
    float4 a = {0.f, 0.f, 0.f, 0.f};
    for (int e = e0; e < e1; e++) {
        int id = g_eid[e];
        float4 v = *(const float4*)(ef + (size_t)id * ED + lane * 4);
        a.x += v.x; a.y += v.y; a.z += v.z; a.w += v.w;
    }
    *(float4*)(g_eagg + (size_t)w * ED + lane * 4) = a;
}

// ---------------- static columns of fused GEMM input (once per launch) ------
// layout per row v: [0,FIN)=x  [FIN,2FIN)=inv*na  [2FIN,2FIN+64)=inv*eagg
//                   [2FIN+64]=indicator  rest=0 ; pad rows fully 0
template <int KP, int FIN>
__global__ void k_static(float* __restrict__ XC) {
    int t = blockIdx.x * blockDim.x + threadIdx.x;
    if (t >= NP * KP) return;
    int v = t / KP, col = t - v * KP;
    float* p = XC + (size_t)v * KP + col;
    if (v >= NN) { *p = 0.f; return; }
    if (col < 2 * FIN) return;                 // dynamic: written by gather each layer
    int dg = g_cnt[v];
    float val = 0.f;
    if (col < 2 * FIN + 64) {
        float inv = 1.f / (float)max(dg, 1);
        val = inv * g_eagg[(size_t)v * ED + (col - 2 * FIN)];
    } else if (col == 2 * FIN + 64) {
        val = (dg > 0) ? 1.f : 0.f;
    }
    *p = val;
}

// ---------------- per-layer: copy x + gather mean of src rows into XC -------
template <int NC4, int FIN, int KP>
__global__ void k_gather(const float* __restrict__ X, int ldx, float* __restrict__ XC) {
    int w = (blockIdx.x * blockDim.x + threadIdx.x) >> 5;
    int lane = threadIdx.x & 31;
    if (w >= NN) return;
    int e0 = g_base[w], e1 = g_base[w + 1];
    int c0 = lane, c1 = lane + 32;
    float4 a0 = {0.f, 0.f, 0.f, 0.f};
    float4 a1 = {0.f, 0.f, 0.f, 0.f};
    for (int e = e0; e < e1; e++) {
        int s = g_src[e];
        const float4* row = (const float4*)(X + (size_t)s * ldx);
        if (c0 < NC4) {
            float4 v = row[c0];
            a0.x += v.x; a0.y += v.y; a0.z += v.z; a0.w += v.w;
        }
        if (NC4 > 32 && c1 < NC4) {
            float4 v = row[c1];
            a1.x += v.x; a1.y += v.y; a1.z += v.z; a1.w += v.w;
        }
    }
    float inv = 1.f / fmaxf((float)(e1 - e0), 1.f);
    float4* out = (float4*)(XC + (size_t)w * KP);
    const float4* xrow = (const float4*)(X + (size_t)w * ldx);
    if (c0 < NC4) {
        out[c0] = xrow[c0];
        float4 r; r.x = a0.x * inv; r.y = a0.y * inv; r.z = a0.z * inv; r.w = a0.w * inv;
        out[FIN / 4 + c0] = r;
    }
    if (NC4 > 32 && c1 < NC4) {
        out[c1] = xrow[c1];
        float4 r; r.x = a1.x * inv; r.y = a1.y * inv; r.z = a1.z * inv; r.w = a1.w * inv;
        out[FIN / 4 + c1] = r;
    }
}

// ---------------- build fused weight Wc = [Wa_self | Wa_h@Wm_n | Wa_h@Wm_e | Wa_h@bm]
__global__ void k_wc(const float* __restrict__ Wm, const float* __restrict__ bm,
                     const float* __restrict__ Wa, float* __restrict__ Wc,
                     int Fin, int Fm, int Fout, int Kp) {
    int col = blockIdx.x * blockDim.x + threadIdx.x;
    int j = blockIdx.y;
    int K1 = 2 * Fin + ED + 1;
    if (col >= K1 || j >= Fout) return;
    int WmK = Fin + ED;
    int WaK = Fin + Fm;
    const float* wah = Wa + (size_t)j * WaK + Fin;
    float val;
    if (col < Fin) {
        val = Wa[(size_t)j * WaK + col];
    } else if (col < 2 * Fin) {
        int i = col - Fin;
        float s = 0.f;
        for (int t = 0; t < Fm; t++) s += wah[t] * Wm[(size_t)t * WmK + i];
        val = s;
    } else if (col < 2 * Fin + ED) {
        int i = col - 2 * Fin;
        float s = 0.f;
        for (int t = 0; t < Fm; t++) s += wah[t] * Wm[(size_t)t * WmK + Fin + i];
        val = s;
    } else {
        float s = 0.f;
        for (int t = 0; t < Fm; t++) s += wah[t] * bm[t];
        val = s;
    }
    Wc[(size_t)j * Kp + col] = val;
}

// ---------------- tensor-core tf32x3 GEMM: C = relu(Xc @ Wc^T + bias) -------
// BM=128, BN=64, BK=16; 256 threads = 8 warps in 4(m) x 2(n); warp tile 32x32.
// mma.sync.m16n8k8 tf32 with 3-term split (hi*hi + lo*hi + hi*lo) ~ fp32 precision.

__device__ __forceinline__ void split_tf32(float f, uint32_t& hi, uint32_t& lo) {
    asm("cvt.rna.tf32.f32 %0, %1;" : "=r"(hi) : "f"(f));
    float r = f - __uint_as_float(hi);
    asm("cvt.rna.tf32.f32 %0, %1;" : "=r"(lo) : "f"(r));
}

__device__ __forceinline__ void mma_tf32(float* c, const uint32_t* a, const uint32_t* b) {
    asm volatile(
        "mma.sync.aligned.m16n8k8.row.col.f32.tf32.tf32.f32 "
        "{%0,%1,%2,%3}, {%4,%5,%6,%7}, {%8,%9}, {%0,%1,%2,%3};"
        : "+f"(c[0]), "+f"(c[1]), "+f"(c[2]), "+f"(c[3])
        : "r"(a[0]), "r"(a[1]), "r"(a[2]), "r"(a[3]), "r"(b[0]), "r"(b[1]));
}

__global__ __launch_bounds__(256) void k_gemm_tc(
    const float* __restrict__ A, const float* __restrict__ B,
    const float* __restrict__ bias, float* __restrict__ C,
    int M, int Nout, int Kp, int ldc) {
    __shared__ float As[16][136];   // [k][m], stride 136 -> conflict-free frag loads
    __shared__ float Bs[64][20];    // [n][k], stride 20  -> conflict-free frag loads
    const int m0 = blockIdx.x * 128;
    const int n0 = blockIdx.y * 64;
    const int tid = threadIdx.x;
    const int lane = tid & 31, wid = tid >> 5;
    const int mw = wid >> 1, nw = wid & 1;     // 4 x 2 warp grid
    const int g = lane >> 2, t4 = lane & 3;

    float acc[2][4][4];
#pragma unroll
    for (int i = 0; i < 2; i++)
#pragma unroll
        for (int j = 0; j < 4; j++)
#pragma unroll
            for (int e = 0; e < 4; e++) acc[i][j][e] = 0.f;

    for (int k0 = 0; k0 < Kp; k0 += 16) {
        // stage A tile: 128 x 16
#pragma unroll
        for (int i = 0; i < 2; i++) {
            int idx = tid + i * 256;
            int r = idx >> 2, kq = (idx & 3) << 2;
            float4 v = *(const float4*)(A + (size_t)(m0 + r) * Kp + (k0 + kq));
            As[kq + 0][r] = v.x; As[kq + 1][r] = v.y;
            As[kq + 2][r] = v.z; As[kq + 3][r] = v.w;
        }
        // stage B tile: 64 x 16
        {
            int r = tid >> 2, kq = (tid & 3) << 2;
            float4 v = *(const float4*)(B + (size_t)(n0 + r) * Kp + (k0 + kq));
            Bs[r][kq + 0] = v.x; Bs[r][kq + 1] = v.y;
            Bs[r][kq + 2] = v.z; Bs[r][kq + 3] = v.w;
        }
        __syncthreads();

#pragma unroll
        for (int ks = 0; ks < 16; ks += 8) {
            uint32_t ahi[2][4], alo[2][4], bhi[4][2], blo[4][2];
#pragma unroll
            for (int j = 0; j < 4; j++) {
                int nn = nw * 32 + j * 8 + g;
                split_tf32(Bs[nn][ks + t4],     bhi[j][0], blo[j][0]);
                split_tf32(Bs[nn][ks + t4 + 4], bhi[j][1], blo[j][1]);
            }
#pragma unroll
            for (int i = 0; i < 2; i++) {
                int rr = mw * 32 + i * 16 + g;
                split_tf32(As[ks + t4][rr],          ahi[i][0], alo[i][0]);
                split_tf32(As[ks + t4][rr + 8],      ahi[i][1], alo[i][1]);
                split_tf32(As[ks + t4 + 4][rr],      ahi[i][2], alo[i][2]);
                split_tf32(As[ks + t4 + 4][rr + 8],  ahi[i][3], alo[i][3]);
            }
#pragma unroll
            for (int i = 0; i < 2; i++)
#pragma unroll
                for (int j = 0; j < 4; j++) {
                    mma_tf32(acc[i][j], ahi[i], bhi[j]);
                    mma_tf32(acc[i][j], alo[i], bhi[j]);
                    mma_tf32(acc[i][j], ahi[i], blo[j]);
                }
        }
        __syncthreads();
    }

    // epilogue: bias + relu
#pragma unroll
    for (int i = 0; i < 2; i++) {
#pragma unroll
        for (int j = 0; j < 4; j++) {
            int ncol = n0 + nw * 32 + j * 8 + 2 * t4;
            if (ncol >= Nout) continue;            // Nout multiple of 8: pair safe
            float b0 = bias[ncol], b1 = bias[ncol + 1];
            int mrow = m0 + mw * 32 + i * 16 + g;
            if (mrow < M) {
                float2 r0 = {fmaxf(acc[i][j][0] + b0, 0.f), fmaxf(acc[i][j][1] + b1, 0.f)};
                *(float2*)(C + (size_t)mrow * ldc + ncol) = r0;
            }
            if (mrow + 8 < M) {
                float2 r1 = {fmaxf(acc[i][j][2] + b0, 0.f), fmaxf(acc[i][j][3] + b1, 0.f)};
                *(float2*)(C + (size_t)(mrow + 8) * ldc + ncol) = r1;
            }
        }
    }
}

// ---------------- driver ----------------------------------------------------
extern "C" void kernel_launch(void* const* d_in, const int* in_sizes, int n_in,
                              void* d_out, int out_size) {
    const float* nf  = (const float*)d_in[0];
    const float* ef  = (const float*)d_in[1];
    const float* Wm1 = (const float*)d_in[2];  const float* bm1 = (const float*)d_in[3];
    const float* Wa1 = (const float*)d_in[4];  const float* ba1 = (const float*)d_in[5];
    const float* Wm2 = (const float*)d_in[6];  const float* bm2 = (const float*)d_in[7];
    const float* Wa2 = (const float*)d_in[8];  const float* ba2 = (const float*)d_in[9];
    const float* Wm3 = (const float*)d_in[10]; const float* bm3 = (const float*)d_in[11];
    const float* Wa3 = (const float*)d_in[12]; const float* ba3 = (const float*)d_in[13];
    const int* src = (const int*)d_in[14];
    const int* dst = (const int*)d_in[15];
    float* out = (float*)d_out;

    float *p_h1, *p_h2, *p_xc1, *p_xc2, *p_wc1, *p_wc2, *p_wc3;
    int *p_cnt, *p_fill;
    cudaGetSymbolAddress((void**)&p_cnt,  g_cnt);
    cudaGetSymbolAddress((void**)&p_fill, g_fill);
    cudaGetSymbolAddress((void**)&p_h1,   g_h1);
    cudaGetSymbolAddress((void**)&p_h2,   g_h2);
    cudaGetSymbolAddress((void**)&p_xc1,  g_xc1);
    cudaGetSymbolAddress((void**)&p_xc2,  g_xc2);
    cudaGetSymbolAddress((void**)&p_wc1,  g_wc1);
    cudaGetSymbolAddress((void**)&p_wc2,  g_wc2);
    cudaGetSymbolAddress((void**)&p_wc3,  g_wc3);

    const int GW = (NN * 32 + 255) / 256;   // warp-per-node grids

    // ---- CSR build (int atomics only; ~2.4M ops) ----
    k_zero_i<<<(NP + 255) / 256, 256>>>(p_cnt, NP);
    k_zero_i<<<(NP + 255) / 256, 256>>>(p_fill, NP);
    k_count<<<(NE + 255) / 256, 256>>>(dst);
    k_scan1<<<NB, 512>>>();
    k_scan2<<<1, 32>>>();
    k_scan3<<<(NP + 255) / 256, 256>>>();
    k_fill<<<(NE + 255) / 256, 256>>>(src, dst);

    // ---- graph-constant: edge-feature aggregation + static Xc columns ----
    k_gather_e<<<GW, 256>>>(ef);
    k_static<208,  64><<<(NP * 208 + 255) / 256, 256>>>(p_xc1);
    k_static<384, 152><<<(NP * 384 + 255) / 256, 256>>>(p_xc2);

    // ---- fused weights ----
    k_zero_f<<<(192 * 208 + 255) / 256, 256>>>(p_wc1, 192 * 208);
    k_zero_f<<<(192 * 384 + 255) / 256, 256>>>(p_wc2, 192 * 384);
    k_zero_f<<<(64 * 384 + 255) / 256, 256>>>(p_wc3, 64 * 384);
    k_wc<<<dim3(2, 152), 128>>>(Wm1, bm1, Wa1, p_wc1, 64, 152, 152, 208);
    k_wc<<<dim3(3, 152), 128>>>(Wm2, bm2, Wa2, p_wc2, 152, 152, 152, 384);
    k_wc<<<dim3(3, 64), 128>>>(Wm3, bm3, Wa3, p_wc3, 152, 64, 64, 384);

    // ---- layer 1 (64 -> 152) ----
    k_gather<16, 64, 208><<<GW, 256>>>(nf, 64, p_xc1);
    k_gemm_tc<<<dim3(NP / 128, 3), 256>>>(p_xc1, p_wc1, ba1, p_h1, NN, 152, 208, HID);

    // ---- layer 2 (152 -> 152) ----
    k_gather<38, 152, 384><<<GW, 256>>>(p_h1, HID, p_xc2);
    k_gemm_tc<<<dim3(NP / 128, 3), 256>>>(p_xc2, p_wc2, ba2, p_h2, NN, 152, 384, HID);

    // ---- layer 3 (152 -> 64) ----
    k_gather<38, 152, 384><<<GW, 256>>>(p_h2, HID, p_xc2);
    k_gemm_tc<<<dim3(NP / 128, 1), 256>>>(p_xc2, p_wc3, ba3, out, NN, 64, 384, 64);
}